// round 14
// baseline (speedup 1.0000x reference)
#include <cuda_runtime.h>

#define Bc   2
#define Lc   512
#define DIMc 128
#define Kc   32
#define EPSc 1e-5f
#define RPB  4      // rows per block in the GEMV kernel
#define FTI  8      // fuse: i-rows per block (one per warp)
#define FTJ  32     // fuse: j-rows per block (smem tile)

// Scratch: 6 x 512KB = 3MB, L2-resident.
__device__ float g_out_mean[Bc * Lc * DIMc];
__device__ float g_in_mean [Bc * Lc * DIMc];
__device__ float g_out_agg [Bc * Lc * DIMc];
__device__ float g_in_agg  [Bc * Lc * DIMc];
__device__ float g_go      [Bc * Lc * DIMc];  // out_agg @ Wg_o + b_g
__device__ float g_gi      [Bc * Lc * DIMc];  // in_agg  @ Wg_i

__device__ __forceinline__ float tanh_approx(float x) {
    float r;
    asm("tanh.approx.f32 %0, %1;" : "=f"(r) : "f"(x));
    return r;
}

// ---- packed f32x2 helpers (FFMA2/FADD2/FMUL2 — PTX-only on sm_103a) ----
__device__ __forceinline__ unsigned long long f2u(float2 v) {
    unsigned long long u;
    asm("mov.b64 %0, {%1, %2};" : "=l"(u) : "f"(v.x), "f"(v.y));
    return u;
}
__device__ __forceinline__ float2 u2f(unsigned long long u) {
    float2 v;
    asm("mov.b64 {%0, %1}, %2;" : "=f"(v.x), "=f"(v.y) : "l"(u));
    return v;
}
__device__ __forceinline__ float2 add2(float2 a, float2 b) {
    unsigned long long r, x = f2u(a), y = f2u(b);
    asm("add.rn.f32x2 %0, %1, %2;" : "=l"(r) : "l"(x), "l"(y));
    return u2f(r);
}
__device__ __forceinline__ float2 mul2(float2 a, float2 b) {
    unsigned long long r, x = f2u(a), y = f2u(b);
    asm("mul.rn.f32x2 %0, %1, %2;" : "=l"(r) : "l"(x), "l"(y));
    return u2f(r);
}
__device__ __forceinline__ float2 fma2(float2 a, float2 b, float2 c) {
    unsigned long long r, x = f2u(a), y = f2u(b), z = f2u(c);
    asm("fma.rn.f32x2 %0, %1, %2, %3;" : "=l"(r) : "l"(x), "l"(y), "l"(z));
    return u2f(r);
}

// ---------------------------------------------------------------------------
// Kernel 1: gather-means. One block per global row (b*L + r), 256 threads.
// ---------------------------------------------------------------------------
__global__ void __launch_bounds__(256) means_kernel(const float* __restrict__ pair)
{
    __shared__ float sm[2][2][DIMc];   // [arr][h][d]
    const int rr = blockIdx.x;         // b*L + r
    const int b  = rr >> 9;
    const int rl = rr & (Lc - 1);
    const int t  = threadIdx.x;
    const int d  = t & 127;
    const int h  = t >> 7;

    float so = 0.f, si = 0.f;
    #pragma unroll
    for (int kk = 0; kk < Kc / 2; kk++) {
        const int k   = h * (Kc / 2) + kk;
        const int idx = (k * (Lc - 1)) / (Kc - 1);   // exact floor(linspace)
        so += pair[((size_t)rr * Lc + idx) * DIMc + d];             // [b,r,idx,d]
        si += pair[(((size_t)b * Lc + idx) * Lc + rl) * DIMc + d];  // [b,idx,r,d]
    }
    sm[0][h][d] = so;
    sm[1][h][d] = si;
    __syncthreads();
    if (h == 0) {
        g_out_mean[rr * DIMc + d] = (sm[0][0][d] + sm[0][1][d]) * (1.f / Kc);
        g_in_mean [rr * DIMc + d] = (sm[1][0][d] + sm[1][1][d]) * (1.f / Kc);
    }
}

// ---------------------------------------------------------------------------
// Kernel 2: agg GEMVs + gate GEMVs chained through smem.
// ---------------------------------------------------------------------------
__global__ void __launch_bounds__(256) agg_gate_kernel(
    const float* __restrict__ W_out, const float* __restrict__ b_out,
    const float* __restrict__ W_in,  const float* __restrict__ b_in,
    const float* __restrict__ W_g,   const float* __restrict__ b_g)
{
    __shared__ float s_om[RPB][DIMc];
    __shared__ float s_im[RPB][DIMc];
    __shared__ float s_a [2][RPB][DIMc];   // [0]=oa, [1]=ia

    const int t  = threadIdx.x;
    const int d  = t & 127;
    const int h  = t >> 7;
    const int r0 = blockIdx.x * RPB;

    for (int s = t; s < RPB * DIMc; s += 256) {
        const int r = s >> 7, dd = s & 127;
        s_om[r][dd] = g_out_mean[(r0 + r) * DIMc + dd];
        s_im[r][dd] = g_in_mean [(r0 + r) * DIMc + dd];
    }
    __syncthreads();

    {
        const float* __restrict__ W = h ? W_in : W_out;
        const float (*src)[DIMc]    = h ? s_im : s_om;
        float* __restrict__ dst     = h ? g_in_agg : g_out_agg;
        float acc[RPB];
        const float bv = h ? b_in[d] : b_out[d];
        #pragma unroll
        for (int r = 0; r < RPB; r++) acc[r] = bv;
        #pragma unroll 8
        for (int m = 0; m < DIMc; m++) {
            const float w = W[m * DIMc + d];
            #pragma unroll
            for (int r = 0; r < RPB; r++)
                acc[r] = fmaf(src[r][m], w, acc[r]);
        }
        #pragma unroll
        for (int r = 0; r < RPB; r++) {
            dst[(r0 + r) * DIMc + d] = acc[r];
            s_a[h][r][d] = acc[r];
        }
    }
    __syncthreads();

    {
        const float* __restrict__ W = W_g + h * DIMc * DIMc;
        float* __restrict__ dst     = h ? g_gi : g_go;
        float acc[RPB];
        const float bv = h ? 0.f : b_g[d];
        #pragma unroll
        for (int r = 0; r < RPB; r++) acc[r] = bv;
        #pragma unroll 8
        for (int m = 0; m < DIMc; m++) {
            const float w = W[m * DIMc + d];
            #pragma unroll
            for (int r = 0; r < RPB; r++)
                acc[r] = fmaf(s_a[h][r][m], w, acc[r]);
        }
        #pragma unroll
        for (int r = 0; r < RPB; r++)
            dst[(r0 + r) * DIMc + d] = acc[r];
    }
}

// ---------------------------------------------------------------------------
// Kernel 3: fused gate/blend + LayerNorm. R7 structure (16 lanes/row, one
// i-row per warp, fp32 smem j-tiles) with packed f32x2 math everywhere
// except the per-element tanh.
// ---------------------------------------------------------------------------
__device__ __forceinline__ void row_ln(
    const float2* p, const float2* oa, const float2* ia,
    const float2* go, const float2* gi,
    const float2* lw, const float2* lb, float2* o)
{
    const float2 cP = {0.5f, 0.5f};
    const float2 cM = {-0.5f, -0.5f};
    float2 x[4];
    #pragma unroll
    for (int q = 0; q < 4; q++) {
        const float2 z  = add2(go[q], gi[q]);
        const float2 zh = mul2(z, cP);
        float2 th;
        th.x = tanh_approx(zh.x);
        th.y = tanh_approx(zh.y);
        const float2 g = fma2(th, cP, cP);   // sigmoid(z)
        const float2 h = fma2(th, cM, cP);   // 1 - sigmoid(z)
        const float2 u = add2(oa[q], ia[q]);
        const float2 t = mul2(h, p[q]);      // (1-g)*p
        x[q] = fma2(g, u, t);                // g*u + (1-g)*p
    }
    const float2 s2 = add2(add2(x[0], x[1]), add2(x[2], x[3]));
    float2 q2 = mul2(x[0], x[0]);
    q2 = fma2(x[1], x[1], q2);
    q2 = fma2(x[2], x[2], q2);
    q2 = fma2(x[3], x[3], q2);
    float s = s2.x + s2.y, sq = q2.x + q2.y;
    #pragma unroll
    for (int of = 8; of; of >>= 1) {
        s  += __shfl_xor_sync(0xFFFFFFFFu, s,  of);
        sq += __shfl_xor_sync(0xFFFFFFFFu, sq, of);
    }
    const float mean = s * (1.f / DIMc);
    const float rstd = rsqrtf(sq * (1.f / DIMc) - mean * mean + EPSc);
    const float2 r2  = {rstd, rstd};
    const float2 nm2 = {-mean, -mean};
    #pragma unroll
    for (int q = 0; q < 4; q++) {
        const float2 a = mul2(lw[q], r2);        // rstd*lw
        const float2 c = fma2(nm2, a, lb[q]);    // lb - mean*rstd*lw
        o[q] = fma2(x[q], a, c);                 // x*a + c
    }
}

__device__ __forceinline__ void split4(const float4 v0, const float4 v1, float2* d) {
    d[0].x = v0.x; d[0].y = v0.y;
    d[1].x = v0.z; d[1].y = v0.w;
    d[2].x = v1.x; d[2].y = v1.y;
    d[3].x = v1.z; d[3].y = v1.w;
}

__global__ void __launch_bounds__(256) fuse_ln_kernel(
    const float* __restrict__ pair,
    const float* __restrict__ ln_w,
    const float* __restrict__ ln_b,
    float* __restrict__ out)
{
    __shared__ float s_ia[FTJ][DIMc];
    __shared__ float s_gi[FTJ][DIMc];

    const int t    = threadIdx.x;
    const int tile = blockIdx.x;             // b*(64*16) + it*16 + jt
    const int b    = tile >> 10;
    const int it   = (tile >> 4) & 63;
    const int jt   = tile & 15;
    const int i0   = it * FTI, j0 = jt * FTJ;

    const float4* __restrict__ ia4 = (const float4*)g_in_agg;
    const float4* __restrict__ gi4 = (const float4*)g_gi;

    #pragma unroll
    for (int s = t; s < FTJ * 32; s += 256) {
        const int row = s >> 5, c = s & 31;
        ((float4*)s_ia[row])[c] = ia4[(b * Lc + j0 + row) * 32 + c];
        ((float4*)s_gi[row])[c] = gi4[(b * Lc + j0 + row) * 32 + c];
    }
    __syncthreads();

    const int warp = t >> 5;
    const int lane = t & 31;
    const int grp  = lane >> 4;   // which j of the pair this lane serves
    const int lr   = lane & 15;   // 16-lane position within a row (8 floats)
    const int bi   = b * Lc + i0 + warp;

    const float4* __restrict__ oa4 = (const float4*)g_out_agg;
    const float4* __restrict__ go4 = (const float4*)g_go;
    float2 oa[4], go[4], lw[4], lb[4];
    split4(oa4[bi * 32 + lr * 2], oa4[bi * 32 + lr * 2 + 1], oa);
    split4(go4[bi * 32 + lr * 2], go4[bi * 32 + lr * 2 + 1], go);
    split4(((const float4*)ln_w)[lr * 2], ((const float4*)ln_w)[lr * 2 + 1], lw);
    split4(((const float4*)ln_b)[lr * 2], ((const float4*)ln_b)[lr * 2 + 1], lb);

    const float4* __restrict__ p4 = (const float4*)pair;
    float4* __restrict__ o4p = (float4*)out;
    const size_t base = ((size_t)bi * Lc + j0) * 32 + lr * 2;

    #pragma unroll 1
    for (int jj = 0; jj < FTJ; jj += 4) {
        const int jA = jj + grp;          // rows {jj, jj+1} across the warp
        const int jB = jj + 2 + grp;      // rows {jj+2, jj+3}
        const size_t offA = base + (size_t)jA * 32;
        const size_t offB = base + (size_t)jB * 32;

        const float4 pA0 = __ldcs(&p4[offA]);
        const float4 pA1 = __ldcs(&p4[offA + 1]);
        const float4 pB0 = __ldcs(&p4[offB]);
        const float4 pB1 = __ldcs(&p4[offB + 1]);

        // --- rows A ---
        {
            float2 p[4], ia[4], gi[4], o[4];
            split4(pA0, pA1, p);
            split4(((const float4*)s_ia[jA])[lr * 2], ((const float4*)s_ia[jA])[lr * 2 + 1], ia);
            split4(((const float4*)s_gi[jA])[lr * 2], ((const float4*)s_gi[jA])[lr * 2 + 1], gi);
            row_ln(p, oa, ia, go, gi, lw, lb, o);
            float4 o0, o1;
            o0.x = o[0].x; o0.y = o[0].y; o0.z = o[1].x; o0.w = o[1].y;
            o1.x = o[2].x; o1.y = o[2].y; o1.z = o[3].x; o1.w = o[3].y;
            __stcs(&o4p[offA], o0);
            __stcs(&o4p[offA + 1], o1);
        }
        // --- rows B ---
        {
            float2 p[4], ia[4], gi[4], o[4];
            split4(pB0, pB1, p);
            split4(((const float4*)s_ia[jB])[lr * 2], ((const float4*)s_ia[jB])[lr * 2 + 1], ia);
            split4(((const float4*)s_gi[jB])[lr * 2], ((const float4*)s_gi[jB])[lr * 2 + 1], gi);
            row_ln(p, oa, ia, go, gi, lw, lb, o);
            float4 o0, o1;
            o0.x = o[0].x; o0.y = o[0].y; o0.z = o[1].x; o0.w = o[1].y;
            o1.x = o[2].x; o1.y = o[2].y; o1.z = o[3].x; o1.w = o[3].y;
            __stcs(&o4p[offB], o0);
            __stcs(&o4p[offB + 1], o1);
        }
    }
}

extern "C" void kernel_launch(void* const* d_in, const int* in_sizes, int n_in,
                              void* d_out, int out_size) {
    const float* pair  = (const float*)d_in[0];
    const float* W_out = (const float*)d_in[1];
    const float* b_out = (const float*)d_in[2];
    const float* W_in  = (const float*)d_in[3];
    const float* b_in  = (const float*)d_in[4];
    const float* W_g   = (const float*)d_in[5];
    const float* b_g   = (const float*)d_in[6];
    const float* ln_w  = (const float*)d_in[7];
    const float* ln_b  = (const float*)d_in[8];
    float* out = (float*)d_out;

    means_kernel<<<Bc * Lc, 256>>>(pair);
    agg_gate_kernel<<<(Bc * Lc) / RPB, 256>>>(W_out, b_out, W_in, b_in, W_g, b_g);
    fuse_ln_kernel<<<Bc * (Lc / FTI) * (Lc / FTJ), 256>>>(pair, ln_w, ln_b, out);
}